// round 1
// baseline (speedup 1.0000x reference)
#include <cuda_runtime.h>
#include <math.h>

#define Bsz  2048
#define Dd   512
#define Cc   128
#define Tt   151
#define ROWS 16
#define G3D  1536   // 3*D

// ---------------- device scratch (no allocations allowed) ----------------
__device__ float g_h[Bsz * Dd];          // hidden state [B, D]
__device__ float g_G[129 * G3D];         // gi table: embed@W_ih^T + b_ih ; row 128 = b_ih (zero token)
__device__ float g_WhhT[Dd * G3D];       // W_hh transposed: [k][3D]
__device__ float g_WprojT[Dd * Cc];      // W_proj transposed: [k][C]
__device__ int   g_tok[Bsz];             // current token per batch row

// ---------------- setup: transpose weights, init h and tok ----------------
__global__ void setup_kernel(const float* __restrict__ feat,
                             const float* __restrict__ W_hh,
                             const float* __restrict__ W_proj)
{
    int i = blockIdx.x * blockDim.x + threadIdx.x;
    if (i < Bsz * Dd) g_h[i] = feat[i];
    if (i < Dd * G3D) {                    // i = k*G3D + j
        int k = i / G3D, j = i - k * G3D;
        g_WhhT[i] = W_hh[j * Dd + k];
    }
    if (i < Dd * Cc) {                     // i = k*Cc + c
        int k = i / Cc, c = i - k * Cc;
        g_WprojT[i] = W_proj[c * Dd + k];
    }
    if (i < Bsz) g_tok[i] = 128;           // start token -> zero-input row of G
}

// ---------------- gi table: G[c][j] = sum_k embed[c,k]*W_ih[j,k] + b_ih[j] ----------------
__global__ void gi_table_kernel(const float* __restrict__ embed,
                                const float* __restrict__ W_ih,
                                const float* __restrict__ b_ih)
{
    int i = blockIdx.x * blockDim.x + threadIdx.x;   // 129*1536 outputs
    if (i >= 129 * G3D) return;
    int c = i / G3D, j = i - c * G3D;
    float s = b_ih[j];
    if (c < Cc) {
        const float* e = embed + c * Dd;
        const float* w = W_ih + j * Dd;
        float acc = 0.f;
        #pragma unroll 4
        for (int k = 0; k < Dd; k++) acc = fmaf(e[k], w[k], acc);
        s += acc;
    }
    g_G[i] = s;
}

// ---------------- one GRU step, fully fused per block of 16 batch rows ----------------
__global__ void __launch_bounds__(256) step_kernel(const float* __restrict__ b_hh,
                                                   const float* __restrict__ b_proj,
                                                   float* __restrict__ out,
                                                   int t, int wr_tok)
{
    __shared__ float h_sh[ROWS][Dd];          // 32 KB: old h, later reused for h_new
    __shared__ float lg_sh[ROWS][Cc + 1];     // padded (129) -> conflict-free argmax
    __shared__ int   tk_sh[ROWS];

    const int tid  = threadIdx.x;
    const int row0 = blockIdx.x * ROWS;

    // load this block's h rows (coalesced float4) + tokens
    {
        const float4* src = (const float4*)(g_h + row0 * Dd);
        float4*       dst = (float4*)(&h_sh[0][0]);
        for (int i = tid; i < ROWS * Dd / 4; i += 256) dst[i] = src[i];
        if (tid < ROWS) tk_sh[tid] = g_tok[row0 + tid];
    }
    __syncthreads();

    float hnew[2][ROWS];

    // ---- GRU cell: each thread owns columns j = tid and tid+256 across all 16 rows ----
    #pragma unroll 1
    for (int cc = 0; cc < 2; cc++) {
        const int j = cc * 256 + tid;
        float ar[ROWS], az[ROWS], an[ROWS];
        #pragma unroll
        for (int r = 0; r < ROWS; r++) { ar[r] = 0.f; az[r] = 0.f; an[r] = 0.f; }

        const float* wp = g_WhhT + j;          // coalesced across lanes
        #pragma unroll 4
        for (int k = 0; k < Dd; k++) {
            float wr = wp[k * G3D];
            float wz = wp[k * G3D + Dd];
            float wn = wp[k * G3D + 2 * Dd];
            #pragma unroll
            for (int r = 0; r < ROWS; r++) {
                float hv = h_sh[r][k];          // warp broadcast
                ar[r] = fmaf(hv, wr, ar[r]);
                az[r] = fmaf(hv, wz, az[r]);
                an[r] = fmaf(hv, wn, an[r]);
            }
        }

        const float bhr = b_hh[j], bhz = b_hh[Dd + j], bhn = b_hh[2 * Dd + j];
        #pragma unroll
        for (int r = 0; r < ROWS; r++) {
            const float* Grow = g_G + tk_sh[r] * G3D;   // precomputed gi (incl. b_ih)
            float ir  = Grow[j];
            float iz  = Grow[Dd + j];
            float in_ = Grow[2 * Dd + j];
            float rg = 1.f / (1.f + expf(-(ir + ar[r] + bhr)));
            float zg = 1.f / (1.f + expf(-(iz + az[r] + bhz)));
            float ng = tanhf(in_ + rg * (an[r] + bhn));
            hnew[cc][r] = (1.f - zg) * ng + zg * h_sh[r][j];
        }
    }
    __syncthreads();   // everyone done reading old h

    // publish h_new: shared (for proj) + global (for next step)
    #pragma unroll
    for (int cc = 0; cc < 2; cc++) {
        int j = cc * 256 + tid;
        #pragma unroll
        for (int r = 0; r < ROWS; r++) {
            h_sh[r][j] = hnew[cc][r];
            g_h[(row0 + r) * Dd + j] = hnew[cc][r];     // coalesced across lanes
        }
    }
    __syncthreads();

    // ---- projection: thread -> (col c, row-half). 8 rows x 1 col each ----
    const int c    = tid & (Cc - 1);
    const int half = tid >> 7;
    float acc[8];
    #pragma unroll
    for (int r = 0; r < 8; r++) acc[r] = 0.f;
    const float* wq = g_WprojT + c;                      // coalesced across lanes
    #pragma unroll 4
    for (int k = 0; k < Dd; k++) {
        float wv = wq[k * Cc];
        #pragma unroll
        for (int r = 0; r < 8; r++)
            acc[r] = fmaf(h_sh[half * 8 + r][k], wv, acc[r]);   // broadcast
    }
    const float bp = b_proj[c];
    #pragma unroll
    for (int r = 0; r < 8; r++) {
        int   row = half * 8 + r;
        float lg  = acc[r] + bp;
        lg_sh[row][c] = lg;
        out[(size_t)(row0 + row) * Cc * Tt + (size_t)c * Tt + t] = lg;  // [B,C,T]
    }
    __syncthreads();

    // ---- argmax over 128 logits (first-max tie-break, like jnp.argmax) ----
    if (tid < ROWS) {
        float best = lg_sh[tid][0];
        int   bidx = 0;
        #pragma unroll 4
        for (int cq = 1; cq < Cc; cq++) {
            float v = lg_sh[tid][cq];
            if (v > best) { best = v; bidx = cq; }
        }
        g_tok[row0 + tid] = bidx;
        if (wr_tok)
            out[(size_t)Bsz * Cc * Tt + (size_t)(row0 + tid) * Tt + t] = (float)bidx;
    }
}

// ---------------- launch: setup + G table + 151 sequential steps ----------------
extern "C" void kernel_launch(void* const* d_in, const int* in_sizes, int n_in,
                              void* d_out, int out_size)
{
    const float* feat   = (const float*)d_in[0];
    const float* W_ih   = (const float*)d_in[1];
    const float* W_hh   = (const float*)d_in[2];
    const float* b_ih   = (const float*)d_in[3];
    const float* b_hh   = (const float*)d_in[4];
    const float* W_proj = (const float*)d_in[5];
    const float* b_proj = (const float*)d_in[6];
    const float* embed  = (const float*)d_in[7];
    float* out = (float*)d_out;

    // write tokens only if the output buffer includes them (logits [B,C,T] first)
    int wr_tok = (out_size >= Bsz * Cc * Tt + Bsz * Tt) ? 1 : 0;

    setup_kernel<<<(Bsz * Dd + 255) / 256, 256>>>(feat, W_hh, W_proj);
    gi_table_kernel<<<(129 * G3D + 127) / 128, 128>>>(embed, W_ih, b_ih);

    for (int t = 0; t < Tt; t++)
        step_kernel<<<Bsz / ROWS, 256>>>(b_hh, b_proj, out, t, wr_tok);
}

// round 2
// speedup vs baseline: 1.2847x; 1.2847x over previous
#include <cuda_runtime.h>
#include <math.h>

#define Bsz  2048
#define Dd   512
#define Cc   128
#define Tt   151
#define ROWS 16
#define G3D  1536
#define THREADS 512
#define KK   8
#define NTILE (Dd / KK)   // 64

// ---------------- device scratch ----------------
__device__ float g_h[Bsz * Dd];
__device__ float g_G[129 * G3D];        // gi table incl b_ih; row 128 = zero-token
__device__ float g_WhhT[Dd * G3D];      // [k][3D]
__device__ float g_WprojT[Dd * Cc];     // [k][C]
__device__ int   g_tok[Bsz];

// ---------------- PTX helpers ----------------
__device__ __forceinline__ unsigned smem_u32(const void* p) {
    unsigned a;
    asm("{ .reg .u64 t; cvta.to.shared.u64 t, %1; cvt.u32.u64 %0, t; }" : "=r"(a) : "l"(p));
    return a;
}
__device__ __forceinline__ unsigned long long dup2(float w) {
    unsigned long long r;
    asm("mov.b64 %0, {%1, %1};" : "=l"(r) : "f"(w));
    return r;
}
#define FMA2(c, a, b) asm("fma.rn.f32x2 %0, %1, %2, %0;" : "+l"(c) : "l"(a), "l"(b))
__device__ __forceinline__ void unpk(unsigned long long v, float& lo, float& hi) {
    asm("mov.b64 {%0, %1}, %2;" : "=f"(lo), "=f"(hi) : "l"(v));
}
__device__ __forceinline__ void lds2x64(unsigned long long& a, unsigned long long& b, unsigned addr) {
    asm volatile("ld.shared.v2.b64 {%0, %1}, [%2];" : "=l"(a), "=l"(b) : "r"(addr));
}
__device__ __forceinline__ float ldsf(unsigned addr) {
    float v; asm volatile("ld.shared.f32 %0, [%1];" : "=f"(v) : "r"(addr)); return v;
}
__device__ __forceinline__ void cp16(unsigned dst, const float* src) {
    asm volatile("cp.async.cg.shared.global [%0], [%1], 16;" :: "r"(dst), "l"(src));
}
#define CP_COMMIT() asm volatile("cp.async.commit_group;")
#define CP_WAIT0()  asm volatile("cp.async.wait_group 0;" ::: "memory")

// ---------------- setup ----------------
__global__ void setup_kernel(const float* __restrict__ feat,
                             const float* __restrict__ W_hh,
                             const float* __restrict__ W_proj)
{
    int i = blockIdx.x * blockDim.x + threadIdx.x;
    if (i < Bsz * Dd) g_h[i] = feat[i];
    if (i < Dd * G3D) { int k = i / G3D, j = i - k * G3D; g_WhhT[i] = W_hh[j * Dd + k]; }
    if (i < Dd * Cc)  { int k = i / Cc,  c = i - k * Cc;  g_WprojT[i] = W_proj[c * Dd + k]; }
    if (i < Bsz) g_tok[i] = 128;
}

__global__ void gi_table_kernel(const float* __restrict__ embed,
                                const float* __restrict__ W_ih,
                                const float* __restrict__ b_ih)
{
    int i = blockIdx.x * blockDim.x + threadIdx.x;
    if (i >= 129 * G3D) return;
    int c = i / G3D, j = i - c * G3D;
    float s = b_ih[j];
    if (c < Cc) {
        const float* e = embed + c * Dd;
        const float* w = W_ih + j * Dd;
        float acc = 0.f;
        #pragma unroll 4
        for (int k = 0; k < Dd; k++) acc = fmaf(e[k], w[k], acc);
        s += acc;
    }
    g_G[i] = s;
}

// shared layout (floats):
//   hT  [512*16]  @ 0       h_old transposed: hT[k*16 + r]
//   hN  [512*16]  @ 8192    h_new transposed
//   wt  [2][8*1536] @ 16384 double-buffered W_hh k-tiles
//   lg  [16*128]  @ 40960   logits
//   tk  [16]      @ 43008
#define SM_FLOATS (43008 + 16)
#define SM_BYTES  (SM_FLOATS * 4)

__global__ void __launch_bounds__(THREADS, 1)
step_kernel(const float* __restrict__ b_hh,
            const float* __restrict__ b_proj,
            float* __restrict__ out,
            int t, int wr_tok)
{
    extern __shared__ float sm[];
    const unsigned base = smem_u32(sm);
    const unsigned HT = base;
    const unsigned HN = base + 32768;
    const unsigned WT = base + 65536;
    float* lg = sm + 40960;
    int*   tk = (int*)(sm + 43008);

    const int tid  = threadIdx.x;
    const int row0 = blockIdx.x * ROWS;

    // prefetch W tile 0
    {
        const float* src = g_WhhT;
        #pragma unroll
        for (int i = 0; i < 6; i++)
            cp16(WT + (tid + i * 512) * 16, src + (tid + i * 512) * 4);
        CP_COMMIT();
    }

    // load h (k = tid) -> hT transposed, via float4 stores
    {
        float tmp[ROWS];
        #pragma unroll
        for (int r = 0; r < ROWS; r++) tmp[r] = g_h[(row0 + r) * Dd + tid];
        float4* d = (float4*)sm;   // hT at offset 0
        #pragma unroll
        for (int q = 0; q < 4; q++)
            d[tid * 4 + q] = make_float4(tmp[4*q], tmp[4*q+1], tmp[4*q+2], tmp[4*q+3]);
    }
    if (tid < ROWS) tk[tid] = g_tok[row0 + tid];

    // ---- gate GEMM: thread owns column j = tid; acc packed over row pairs ----
    unsigned long long ar[8], az[8], an[8];
    #pragma unroll
    for (int q = 0; q < 8; q++) { ar[q] = 0ull; az[q] = 0ull; an[q] = 0ull; }

    for (int tl = 0; tl < NTILE; tl++) {
        CP_WAIT0();
        __syncthreads();
        if (tl + 1 < NTILE) {
            const float* src = g_WhhT + (tl + 1) * KK * G3D;
            unsigned dst = WT + ((tl + 1) & 1) * 49152;
            #pragma unroll
            for (int i = 0; i < 6; i++)
                cp16(dst + (tid + i * 512) * 16, src + (tid + i * 512) * 4);
            CP_COMMIT();
        }
        unsigned wb = WT + (tl & 1) * 49152 + tid * 4;
        unsigned ha = HT + tl * KK * 64;
        #pragma unroll
        for (int kk = 0; kk < KK; kk++) {
            unsigned long long h0,h1,h2,h3,h4,h5,h6,h7;
            lds2x64(h0, h1, ha);
            lds2x64(h2, h3, ha + 16);
            lds2x64(h4, h5, ha + 32);
            lds2x64(h6, h7, ha + 48);
            float wr = ldsf(wb);
            float wz = ldsf(wb + 2048);
            float wn = ldsf(wb + 4096);
            unsigned long long w2;
            w2 = dup2(wr);
            FMA2(ar[0], h0, w2); FMA2(ar[1], h1, w2); FMA2(ar[2], h2, w2); FMA2(ar[3], h3, w2);
            FMA2(ar[4], h4, w2); FMA2(ar[5], h5, w2); FMA2(ar[6], h6, w2); FMA2(ar[7], h7, w2);
            w2 = dup2(wz);
            FMA2(az[0], h0, w2); FMA2(az[1], h1, w2); FMA2(az[2], h2, w2); FMA2(az[3], h3, w2);
            FMA2(az[4], h4, w2); FMA2(az[5], h5, w2); FMA2(az[6], h6, w2); FMA2(az[7], h7, w2);
            w2 = dup2(wn);
            FMA2(an[0], h0, w2); FMA2(an[1], h1, w2); FMA2(an[2], h2, w2); FMA2(an[3], h3, w2);
            FMA2(an[4], h4, w2); FMA2(an[5], h5, w2); FMA2(an[6], h6, w2); FMA2(an[7], h7, w2);
            ha += 64;
            wb += 6144;
        }
    }

    // ---- gate nonlinearity + h update (j = tid for all 16 rows) ----
    {
        const int j = tid;
        const float bhr = b_hh[j], bhz = b_hh[Dd + j], bhn = b_hh[2 * Dd + j];
        float hnew[ROWS];
        #pragma unroll
        for (int q = 0; q < 8; q++) {
            float a0, a1, z0, z1, n0, n1;
            unpk(ar[q], a0, a1);
            unpk(az[q], z0, z1);
            unpk(an[q], n0, n1);
            #pragma unroll
            for (int s = 0; s < 2; s++) {
                int r = 2 * q + s;
                const float* Gr = g_G + tk[r] * G3D + j;
                float ir = Gr[0], iz = Gr[Dd], in_ = Gr[2 * Dd];
                float av = s ? a1 : a0;
                float zv = s ? z1 : z0;
                float nv = s ? n1 : n0;
                float rg = 1.f / (1.f + expf(-(ir + av + bhr)));
                float zg = 1.f / (1.f + expf(-(iz + zv + bhz)));
                float ng = tanhf(in_ + rg * (nv + bhn));
                float ho = sm[j * 16 + r];               // hT[j][r]
                hnew[r]  = (1.f - zg) * ng + zg * ho;
            }
        }
        float4* d = (float4*)(sm + 8192);                // hN
        #pragma unroll
        for (int q = 0; q < 4; q++)
            d[j * 4 + q] = make_float4(hnew[4*q], hnew[4*q+1], hnew[4*q+2], hnew[4*q+3]);
        #pragma unroll
        for (int r = 0; r < ROWS; r++)
            g_h[(row0 + r) * Dd + j] = hnew[r];
    }
    __syncthreads();

    // ---- projection: c = tid&127, group g owns rows 4g..4g+3, full k ----
    {
        const int c = tid & (Cc - 1);
        const int g = tid >> 7;
        unsigned long long p0 = 0ull, p1 = 0ull;
        const unsigned hb = HN + g * 16;
        #pragma unroll 4
        for (int k = 0; k < Dd; k++) {
            float wv = g_WprojT[k * Cc + c];
            unsigned long long w2 = dup2(wv);
            unsigned long long a, b;
            lds2x64(a, b, hb + k * 64);
            FMA2(p0, a, w2);
            FMA2(p1, b, w2);
        }
        float v0, v1, v2, v3;
        unpk(p0, v0, v1);
        unpk(p1, v2, v3);
        const float bp = b_proj[c];
        float vv[4] = { v0 + bp, v1 + bp, v2 + bp, v3 + bp };
        #pragma unroll
        for (int ri = 0; ri < 4; ri++) {
            int row = 4 * g + ri;
            lg[row * Cc + c] = vv[ri];
            out[(size_t)(row0 + row) * Cc * Tt + (size_t)c * Tt + t] = vv[ri];
        }
    }
    __syncthreads();

    // ---- argmax ----
    if (tid < ROWS) {
        float best = lg[tid * Cc];
        int   bidx = 0;
        #pragma unroll 4
        for (int cq = 1; cq < Cc; cq++) {
            float v = lg[tid * Cc + cq];
            if (v > best) { best = v; bidx = cq; }
        }
        g_tok[row0 + tid] = bidx;
        if (wr_tok)
            out[(size_t)Bsz * Cc * Tt + (size_t)(row0 + tid) * Tt + t] = (float)bidx;
    }
}

// ---------------- launch ----------------
extern "C" void kernel_launch(void* const* d_in, const int* in_sizes, int n_in,
                              void* d_out, int out_size)
{
    const float* feat   = (const float*)d_in[0];
    const float* W_ih   = (const float*)d_in[1];
    const float* W_hh   = (const float*)d_in[2];
    const float* b_ih   = (const float*)d_in[3];
    const float* b_hh   = (const float*)d_in[4];
    const float* W_proj = (const float*)d_in[5];
    const float* b_proj = (const float*)d_in[6];
    const float* embed  = (const float*)d_in[7];
    float* out = (float*)d_out;

    int wr_tok = (out_size >= Bsz * Cc * Tt + Bsz * Tt) ? 1 : 0;

    static int smem_set = 0;
    if (!smem_set) {
        cudaFuncSetAttribute(step_kernel, cudaFuncAttributeMaxDynamicSharedMemorySize, SM_BYTES);
        smem_set = 1;
    }

    setup_kernel<<<(Bsz * Dd + 255) / 256, 256>>>(feat, W_hh, W_proj);
    gi_table_kernel<<<(129 * G3D + 127) / 128, 128>>>(embed, W_ih, b_ih);

    for (int t = 0; t < Tt; t++)
        step_kernel<<<Bsz / ROWS, THREADS, SM_BYTES>>>(b_hh, b_proj, out, t, wr_tok);
}

// round 3
// speedup vs baseline: 1.3095x; 1.0192x over previous
#include <cuda_runtime.h>
#include <math.h>

#define Bsz  2048
#define Dd   512
#define Cc   128
#define Tt   151
#define ROWS 16
#define G3D  1536
#define THREADS 1024
#define KK   8
#define NTILE 64      // 512 / 8
#define PKK  32
#define PNT  16       // 512 / 32

// ---------------- device scratch ----------------
__device__ float  g_h[Bsz * Dd];
__device__ float  g_G[129 * G3D];       // gi table incl b_ih; row 128 = zero-token
__device__ float  g_WhhT[Dd * G3D];     // [k][3D]
__device__ float2 g_Wproj2[Dd * Cc];    // [k][c] duplicated (w,w)
__device__ int    g_tok[Bsz];

// ---------------- PTX helpers ----------------
__device__ __forceinline__ unsigned smem_u32(const void* p) {
    unsigned a;
    asm("{ .reg .u64 t; cvta.to.shared.u64 t, %1; cvt.u32.u64 %0, t; }" : "=r"(a) : "l"(p));
    return a;
}
__device__ __forceinline__ unsigned long long dup2(float w) {
    unsigned long long r;
    asm("mov.b64 %0, {%1, %1};" : "=l"(r) : "f"(w));
    return r;
}
#define FMA2(c, a, b) asm("fma.rn.f32x2 %0, %1, %2, %0;" : "+l"(c) : "l"(a), "l"(b))
__device__ __forceinline__ void unpk(unsigned long long v, float& lo, float& hi) {
    asm("mov.b64 {%0, %1}, %2;" : "=f"(lo), "=f"(hi) : "l"(v));
}
__device__ __forceinline__ void lds2x64(unsigned long long& a, unsigned long long& b, unsigned addr) {
    asm volatile("ld.shared.v2.b64 {%0, %1}, [%2];" : "=l"(a), "=l"(b) : "r"(addr));
}
__device__ __forceinline__ unsigned long long lds64(unsigned addr) {
    unsigned long long v;
    asm volatile("ld.shared.b64 %0, [%1];" : "=l"(v) : "r"(addr));
    return v;
}
__device__ __forceinline__ float ldsf(unsigned addr) {
    float v; asm volatile("ld.shared.f32 %0, [%1];" : "=f"(v) : "r"(addr)); return v;
}
__device__ __forceinline__ void cp16(unsigned dst, const float* src) {
    asm volatile("cp.async.cg.shared.global [%0], [%1], 16;" :: "r"(dst), "l"(src));
}
#define CP_COMMIT() asm volatile("cp.async.commit_group;")
#define CP_WAIT0()  asm volatile("cp.async.wait_group 0;" ::: "memory")

// ---------------- setup ----------------
__global__ void setup_kernel(const float* __restrict__ feat,
                             const float* __restrict__ W_hh,
                             const float* __restrict__ W_proj)
{
    int i = blockIdx.x * blockDim.x + threadIdx.x;
    if (i < Bsz * Dd) g_h[i] = feat[i];
    if (i < Dd * G3D) { int k = i / G3D, j = i - k * G3D; g_WhhT[i] = W_hh[j * Dd + k]; }
    if (i < Dd * Cc)  { int k = i / Cc,  c = i - k * Cc;
                        float w = W_proj[c * Dd + k];
                        g_Wproj2[i] = make_float2(w, w); }
    if (i < Bsz) g_tok[i] = 128;
}

__global__ void gi_table_kernel(const float* __restrict__ embed,
                                const float* __restrict__ W_ih,
                                const float* __restrict__ b_ih)
{
    int i = blockIdx.x * blockDim.x + threadIdx.x;
    if (i >= 129 * G3D) return;
    int c = i / G3D, j = i - c * G3D;
    float s = b_ih[j];
    if (c < Cc) {
        const float* e = embed + c * Dd;
        const float* w = W_ih + j * Dd;
        float acc = 0.f;
        #pragma unroll 4
        for (int k = 0; k < Dd; k++) acc = fmaf(e[k], w[k], acc);
        s += acc;
    }
    g_G[i] = s;
}

// shared layout (bytes):
//   hT [512*16 f]      @ 0       h transposed hT[k*16+r]; overwritten in place by h_new
//   W  [2][12288 f]    @ 32768   double-buffered tiles (gate: 8x1536; proj: 32x128 float2)
//   lg [16*128 f]      @ 131072
//   tk [16 i]          @ 139264
#define SM_BYTES (139264 + 64)

__global__ void __launch_bounds__(THREADS, 1)
step_kernel(const float* __restrict__ b_hh,
            const float* __restrict__ b_proj,
            float* __restrict__ out,
            int t, int wr_tok)
{
    extern __shared__ float sm[];
    const unsigned base = smem_u32(sm);
    const unsigned HT = base;
    const unsigned WT = base + 32768;
    float* lg = sm + 32768;
    int*   tk = (int*)(sm + 32768 + 2048);

    const int tid  = threadIdx.x;
    const int j    = tid & 511;       // gate column
    const int rg   = tid >> 9;        // row-half: 0 or 1
    const int r0   = rg * 8;
    const int row0 = blockIdx.x * ROWS;

    // prefetch gate W tile 0 (12288 floats = 3072 x 16B)
    #pragma unroll
    for (int i = 0; i < 3; i++)
        cp16(WT + (tid + i * 1024) * 16, g_WhhT + (tid + i * 1024) * 4);
    CP_COMMIT();

    // load h -> transposed hT[k*16+r]; this thread: k=j, rows r0..r0+7
    {
        float tmp[8];
        #pragma unroll
        for (int r = 0; r < 8; r++) tmp[r] = g_h[(row0 + r0 + r) * Dd + j];
        float4* d = (float4*)sm;
        d[j * 4 + rg * 2 + 0] = make_float4(tmp[0], tmp[1], tmp[2], tmp[3]);
        d[j * 4 + rg * 2 + 1] = make_float4(tmp[4], tmp[5], tmp[6], tmp[7]);
    }
    if (tid < ROWS) tk[tid] = g_tok[row0 + tid];

    // ---- gate GEMM: col j, 8 rows packed as 4 f32x2 accumulators per gate ----
    unsigned long long ar[4], az[4], an[4];
    #pragma unroll
    for (int q = 0; q < 4; q++) { ar[q] = 0ull; az[q] = 0ull; an[q] = 0ull; }

    for (int tl = 0; tl < NTILE; tl++) {
        CP_WAIT0();
        __syncthreads();
        if (tl + 1 < NTILE) {
            const float* src = g_WhhT + (tl + 1) * KK * G3D;
            unsigned dst = WT + ((tl + 1) & 1) * 49152;
            #pragma unroll
            for (int i = 0; i < 3; i++)
                cp16(dst + (tid + i * 1024) * 16, src + (tid + i * 1024) * 4);
            CP_COMMIT();
        }
        const unsigned wb0 = WT + (tl & 1) * 49152 + j * 4;
        const unsigned ha0 = HT + tl * KK * 64 + rg * 32;
        #pragma unroll
        for (int kk = 0; kk < KK; kk++) {
            unsigned long long h0, h1, h2, h3;
            lds2x64(h0, h1, ha0 + kk * 64);
            lds2x64(h2, h3, ha0 + kk * 64 + 16);
            float wr = ldsf(wb0 + kk * 6144);
            float wz = ldsf(wb0 + kk * 6144 + 2048);
            float wn = ldsf(wb0 + kk * 6144 + 4096);
            unsigned long long w2;
            w2 = dup2(wr);
            FMA2(ar[0], h0, w2); FMA2(ar[1], h1, w2); FMA2(ar[2], h2, w2); FMA2(ar[3], h3, w2);
            w2 = dup2(wz);
            FMA2(az[0], h0, w2); FMA2(az[1], h1, w2); FMA2(az[2], h2, w2); FMA2(az[3], h3, w2);
            w2 = dup2(wn);
            FMA2(an[0], h0, w2); FMA2(an[1], h1, w2); FMA2(an[2], h2, w2); FMA2(an[3], h3, w2);
        }
    }
    __syncthreads();    // all threads done reading hT and W buffers

    // prefetch proj W tile 0 (32x128 float2 = 32 KB) into buffer 0
    #pragma unroll
    for (int i = 0; i < 2; i++)
        cp16(WT + (tid + i * 1024) * 16, (const float*)g_Wproj2 + (tid + i * 1024) * 4);
    CP_COMMIT();

    // ---- gate nonlinearity + in-place h update (own slots only) ----
    {
        const float bhr = b_hh[j], bhz = b_hh[Dd + j], bhn = b_hh[2 * Dd + j];
        float hnew[8];
        #pragma unroll
        for (int q = 0; q < 4; q++) {
            float a0, a1, z0, z1, n0, n1;
            unpk(ar[q], a0, a1);
            unpk(az[q], z0, z1);
            unpk(an[q], n0, n1);
            #pragma unroll
            for (int s = 0; s < 2; s++) {
                int rl = 2 * q + s;             // 0..7 within this half
                int r  = r0 + rl;               // 0..15 block-local row
                const float* Gr = g_G + tk[r] * G3D + j;
                float ir = Gr[0], iz = Gr[Dd], in_ = Gr[2 * Dd];
                float av = s ? a1 : a0;
                float zv = s ? z1 : z0;
                float nv = s ? n1 : n0;
                float rgate = 1.f / (1.f + expf(-(ir + av + bhr)));
                float zgate = 1.f / (1.f + expf(-(iz + zv + bhz)));
                float ngate = tanhf(in_ + rgate * (nv + bhn));
                float ho    = sm[j * 16 + r];
                hnew[rl]    = (1.f - zgate) * ngate + zgate * ho;
            }
        }
        float4* d = (float4*)sm;
        d[j * 4 + rg * 2 + 0] = make_float4(hnew[0], hnew[1], hnew[2], hnew[3]);
        d[j * 4 + rg * 2 + 1] = make_float4(hnew[4], hnew[5], hnew[6], hnew[7]);
        #pragma unroll
        for (int r = 0; r < 8; r++)
            g_h[(row0 + r0 + r) * Dd + j] = hnew[r];
    }
    __syncthreads();    // h_new visible to all

    // ---- projection: col c, rows (2g, 2g+1) packed in one f32x2 acc ----
    {
        const int c  = tid & (Cc - 1);
        const int pg = tid >> 7;                 // 0..7 -> rows 2g,2g+1
        unsigned long long p = 0ull;

        for (int pt = 0; pt < PNT; pt++) {
            CP_WAIT0();
            __syncthreads();
            if (pt + 1 < PNT) {
                const float* src = (const float*)(g_Wproj2 + (pt + 1) * PKK * Cc);
                unsigned dst = WT + ((pt + 1) & 1) * 49152;
                #pragma unroll
                for (int i = 0; i < 2; i++)
                    cp16(dst + (tid + i * 1024) * 16, src + (tid + i * 1024) * 4);
                CP_COMMIT();
            }
            const unsigned wpb = WT + (pt & 1) * 49152 + c * 8;
            const unsigned hb  = HT + pt * PKK * 64 + pg * 8;
            #pragma unroll
            for (int kk = 0; kk < PKK; kk++) {
                unsigned long long w2 = lds64(wpb + kk * 1024);   // (w,w) pair
                unsigned long long h2 = lds64(hb + kk * 64);      // rows 2g,2g+1
                FMA2(p, h2, w2);
            }
        }

        float v0, v1;
        unpk(p, v0, v1);
        const float bp = b_proj[c];
        v0 += bp; v1 += bp;
        int rowA = 2 * pg, rowB = 2 * pg + 1;
        lg[rowA * Cc + c] = v0;
        lg[rowB * Cc + c] = v1;
        out[(size_t)(row0 + rowA) * Cc * Tt + (size_t)c * Tt + t] = v0;
        out[(size_t)(row0 + rowB) * Cc * Tt + (size_t)c * Tt + t] = v1;
    }
    __syncthreads();

    // ---- argmax (first-max tie-break) ----
    if (tid < ROWS) {
        float best = lg[tid * Cc];
        int   bidx = 0;
        #pragma unroll 4
        for (int cq = 1; cq < Cc; cq++) {
            float v = lg[tid * Cc + cq];
            if (v > best) { best = v; bidx = cq; }
        }
        g_tok[row0 + tid] = bidx;
        if (wr_tok)
            out[(size_t)Bsz * Cc * Tt + (size_t)(row0 + tid) * Tt + t] = (float)bidx;
    }
}

// ---------------- launch ----------------
extern "C" void kernel_launch(void* const* d_in, const int* in_sizes, int n_in,
                              void* d_out, int out_size)
{
    const float* feat   = (const float*)d_in[0];
    const float* W_ih   = (const float*)d_in[1];
    const float* W_hh   = (const float*)d_in[2];
    const float* b_ih   = (const float*)d_in[3];
    const float* b_hh   = (const float*)d_in[4];
    const float* W_proj = (const float*)d_in[5];
    const float* b_proj = (const float*)d_in[6];
    const float* embed  = (const float*)d_in[7];
    float* out = (float*)d_out;

    int wr_tok = (out_size >= Bsz * Cc * Tt + Bsz * Tt) ? 1 : 0;

    static int smem_set = 0;
    if (!smem_set) {
        cudaFuncSetAttribute(step_kernel, cudaFuncAttributeMaxDynamicSharedMemorySize, SM_BYTES);
        smem_set = 1;
    }

    setup_kernel<<<(Bsz * Dd + 255) / 256, 256>>>(feat, W_hh, W_proj);
    gi_table_kernel<<<(129 * G3D + 127) / 128, 128>>>(embed, W_ih, b_ih);

    for (int t = 0; t < Tt; t++)
        step_kernel<<<Bsz / ROWS, THREADS, SM_BYTES>>>(b_hh, b_proj, out, t, wr_tok);
}